// round 1
// baseline (speedup 1.0000x reference)
#include <cuda_runtime.h>
#include <math.h>

// Problem dims
#define TT 256
#define BB 64
#define EE 768
#define HH 512
#define H2 1024
#define GG 2048            // 4*H
#define TB (TT*BB)         // 16384

// ---------------- scratch (device globals; no allocation allowed) ----------
__device__ float g_pre[2][(size_t)BB*TT*GG];   // [dir][b][t][g]  (bias included)
__device__ float g_gates[2][TT*GG];            // per-step gate pre-activations
__device__ float g_h[2][2][TT*HH];             // [pingpong][dir][t*H+j]
__device__ float g_c[2][TT*HH];                // [dir][t*H+j]
__device__ float g_sents[(size_t)TB*H2];       // [t][b][h2]
__device__ float g_hW[(size_t)TB*H2];          // [t][b][k]
__device__ float g_docmean[BB*H2];
__device__ float g_doc[BB*H2];
__device__ float g_u[BB*H2];                   // w_content + W_sal @ doc
__device__ float g_absp[TT];
__device__ float g_s0[BB*TT];

// ---------------- init -----------------------------------------------------
__global__ void k_zero() {
    int i = blockIdx.x * blockDim.x + threadIdx.x;   // 262144 threads
    if (i < 2*TT*HH) {
        (&g_h[0][0][0])[i] = 0.f;   // pingpong slot 0, both dirs
        (&g_c[0][0])[i]    = 0.f;
    }
}

// ---------------- GEMM: input projection (NT) ------------------------------
// C[r=t*64+b][n] = emb[r] . w_ih[n]  + bias[n], stored permuted to g_pre[dir][b][t][n]
__global__ void __launch_bounds__(256) k_gemm_pre(
    const float* __restrict__ A,      // emb [16384][768]
    const float* __restrict__ W,      // w_ih [2048][768]
    const float* __restrict__ bias,   // [2048]
    int dir)
{
    __shared__ float As[16][68];
    __shared__ float Bs[16][68];
    const int K = EE;
    int tid = threadIdx.x;
    int n0 = blockIdx.x * 64;
    int m0 = blockIdx.y * 64;        // = t*64 ; rows within tile = b
    int lr = tid >> 2;               // 0..63
    int lk = (tid & 3) * 4;          // 0,4,8,12
    int tx = tid & 15, ty = tid >> 4;
    float acc[4][4] = {};
    const float* Ab = A + (size_t)(m0 + lr) * K + lk;
    const float* Wb = W + (size_t)(n0 + lr) * K + lk;
    for (int k0 = 0; k0 < K; k0 += 16) {
        float4 a4 = *(const float4*)(Ab + k0);
        float4 b4 = *(const float4*)(Wb + k0);
        __syncthreads();
        As[lk+0][lr]=a4.x; As[lk+1][lr]=a4.y; As[lk+2][lr]=a4.z; As[lk+3][lr]=a4.w;
        Bs[lk+0][lr]=b4.x; Bs[lk+1][lr]=b4.y; Bs[lk+2][lr]=b4.z; Bs[lk+3][lr]=b4.w;
        __syncthreads();
        #pragma unroll
        for (int kk = 0; kk < 16; kk++) {
            float4 a = *(const float4*)&As[kk][ty*4];
            float4 b = *(const float4*)&Bs[kk][tx*4];
            float av[4] = {a.x,a.y,a.z,a.w};
            float bv[4] = {b.x,b.y,b.z,b.w};
            #pragma unroll
            for (int i=0;i<4;i++)
                #pragma unroll
                for (int j=0;j<4;j++) acc[i][j] = fmaf(av[i], bv[j], acc[i][j]);
        }
    }
    int t = blockIdx.y;   // since m0 = t*64
    #pragma unroll
    for (int i=0;i<4;i++) {
        int b = ty*4 + i;
        float* outp = &g_pre[dir][(((size_t)b*TT + t)*GG) + n0 + tx*4];
        #pragma unroll
        for (int j=0;j<4;j++) outp[j] = acc[i][j] + bias[n0 + tx*4 + j];
    }
}

// ---------------- GEMM: recurrent step (NT), both dirs via grid.z ----------
// gates[dir][t][n] = h_in[dir][t] . w_hh[n] + pre[dir][b][t][n]
__global__ void __launch_bounds__(256) k_gemm_rec(
    const float* __restrict__ w_hh_f,
    const float* __restrict__ w_hh_b,
    int pp, int b_f, int b_b)
{
    __shared__ float As[16][68];
    __shared__ float Bs[16][68];
    const int K = HH;
    int dir = blockIdx.z;
    const float* A = &g_h[pp][dir][0];
    const float* W = dir ? w_hh_b : w_hh_f;
    const float* pre = &g_pre[dir][((size_t)(dir ? b_b : b_f)) * TT * GG];
    int tid = threadIdx.x;
    int n0 = blockIdx.x * 64;
    int m0 = blockIdx.y * 64;
    int lr = tid >> 2;
    int lk = (tid & 3) * 4;
    int tx = tid & 15, ty = tid >> 4;
    float acc[4][4] = {};
    const float* Ab = A + (size_t)(m0 + lr) * K + lk;
    const float* Wb = W + (size_t)(n0 + lr) * K + lk;
    for (int k0 = 0; k0 < K; k0 += 16) {
        float4 a4 = *(const float4*)(Ab + k0);
        float4 b4 = *(const float4*)(Wb + k0);
        __syncthreads();
        As[lk+0][lr]=a4.x; As[lk+1][lr]=a4.y; As[lk+2][lr]=a4.z; As[lk+3][lr]=a4.w;
        Bs[lk+0][lr]=b4.x; Bs[lk+1][lr]=b4.y; Bs[lk+2][lr]=b4.z; Bs[lk+3][lr]=b4.w;
        __syncthreads();
        #pragma unroll
        for (int kk = 0; kk < 16; kk++) {
            float4 a = *(const float4*)&As[kk][ty*4];
            float4 b = *(const float4*)&Bs[kk][tx*4];
            float av[4] = {a.x,a.y,a.z,a.w};
            float bv[4] = {b.x,b.y,b.z,b.w};
            #pragma unroll
            for (int i=0;i<4;i++)
                #pragma unroll
                for (int j=0;j<4;j++) acc[i][j] = fmaf(av[i], bv[j], acc[i][j]);
        }
    }
    #pragma unroll
    for (int i=0;i<4;i++) {
        int row = m0 + ty*4 + i;   // t
        float* outp = &g_gates[dir][(size_t)row*GG + n0 + tx*4];
        const float* pp2 = &pre[(size_t)row*GG + n0 + tx*4];
        #pragma unroll
        for (int j=0;j<4;j++) outp[j] = acc[i][j] + pp2[j];
    }
}

// ---------------- LSTM gate activations + h/c update -----------------------
__global__ void k_act(int pp_out, int b_f, int b_b) {
    int idx = blockIdx.x * blockDim.x + threadIdx.x;  // 262144
    int j   = idx & 511;
    int t   = (idx >> 9) & 255;
    int dir = idx >> 17;
    const float* gg = &g_gates[dir][(size_t)t*GG];
    float vi = gg[j], vf = gg[512+j], vg = gg[1024+j], vo = gg[1536+j];
    float c  = g_c[dir][t*HH + j];
    float si = 1.f/(1.f+expf(-vi));
    float sf = 1.f/(1.f+expf(-vf));
    float so = 1.f/(1.f+expf(-vo));
    float cn = sf*c + si*tanhf(vg);
    float h  = so*tanhf(cn);
    g_c[dir][t*HH + j] = cn;
    g_h[pp_out][dir][t*HH + j] = h;
    int b = dir ? b_b : b_f;
    g_sents[(((size_t)t*BB + b)*H2) + dir*HH + j] = h;
}

// ---------------- doc pipeline ----------------------------------------------
__global__ void k_docmean() {
    int idx = blockIdx.x * blockDim.x + threadIdx.x;  // 65536
    int b = idx >> 10, h = idx & 1023;
    float s = 0.f;
    for (int t = 0; t < TT; t++) s += g_sents[(((size_t)t*BB + b)*H2) + h];
    g_docmean[b*H2 + h] = s * (1.f/TT);
}

__global__ void k_doc(const float* __restrict__ W_fdoc, const float* __restrict__ b_fdoc) {
    int w = blockIdx.x*8 + (threadIdx.x >> 5);  // 65536 warps
    int lane = threadIdx.x & 31;
    int b = w >> 10, n = w & 1023;
    const float* wr = &W_fdoc[(size_t)n*H2];
    const float* dm = &g_docmean[b*H2];
    float s = 0.f;
    for (int k = lane; k < H2; k += 32) s += wr[k]*dm[k];
    #pragma unroll
    for (int o = 16; o > 0; o >>= 1) s += __shfl_down_sync(0xffffffffu, s, o);
    if (lane == 0) g_doc[b*H2 + n] = tanhf(s + b_fdoc[n]);
}

__global__ void k_u(const float* __restrict__ W_sal, const float* __restrict__ w_content) {
    int w = blockIdx.x*8 + (threadIdx.x >> 5);
    int lane = threadIdx.x & 31;
    int b = w >> 10, h = w & 1023;
    const float* wr = &W_sal[(size_t)h*H2];
    const float* dc = &g_doc[b*H2];
    float s = 0.f;
    for (int k = lane; k < H2; k += 32) s += wr[k]*dc[k];
    #pragma unroll
    for (int o = 16; o > 0; o >>= 1) s += __shfl_down_sync(0xffffffffu, s, o);
    if (lane == 0) g_u[b*H2 + h] = s + w_content[h];
}

__global__ void k_absp(const float* __restrict__ pos_emb, const float* __restrict__ w_abs) {
    int t = threadIdx.x;   // 256 threads, 1 block
    float s = 0.f;
    for (int p = 0; p < 100; p++) s += pos_emb[t*100 + p]*w_abs[p];
    g_absp[t] = s;
}

__global__ void k_s0(const float* __restrict__ bias) {
    int w = blockIdx.x*8 + (threadIdx.x >> 5);  // 16384 warps
    int lane = threadIdx.x & 31;
    int b = w >> 8, t = w & 255;
    const float* sp = &g_sents[((size_t)t*BB + b)*H2];
    const float* up = &g_u[b*H2];
    float s = 0.f;
    for (int k = lane; k < H2; k += 32) s += sp[k]*up[k];
    #pragma unroll
    for (int o = 16; o > 0; o >>= 1) s += __shfl_down_sync(0xffffffffu, s, o);
    if (lane == 0) g_s0[b*TT + t] = s + g_absp[t] + bias[0];
}

// ---------------- GEMM NN: hW = sents @ W_nov -------------------------------
__global__ void __launch_bounds__(256) k_gemm_nn(const float* __restrict__ Bm /* W_nov [1024][1024] */)
{
    __shared__ float As[16][68];
    __shared__ float Bs[16][68];
    const int K = H2;
    int tid = threadIdx.x;
    int n0 = blockIdx.x * 64;
    int m0 = blockIdx.y * 64;
    int lrA = tid >> 2;
    int lkA = (tid & 3) * 4;
    int lrB = tid >> 4;             // 0..15  (k row)
    int lcB = (tid & 15) * 4;       // col
    int tx = tid & 15, ty = tid >> 4;
    float acc[4][4] = {};
    const float* Ab = g_sents + (size_t)(m0 + lrA) * K + lkA;
    for (int k0 = 0; k0 < K; k0 += 16) {
        float4 a4 = *(const float4*)(Ab + k0);
        float4 b4 = *(const float4*)(Bm + (size_t)(k0 + lrB)*H2 + n0 + lcB);
        __syncthreads();
        As[lkA+0][lrA]=a4.x; As[lkA+1][lrA]=a4.y; As[lkA+2][lrA]=a4.z; As[lkA+3][lrA]=a4.w;
        *(float4*)&Bs[lrB][lcB] = b4;
        __syncthreads();
        #pragma unroll
        for (int kk = 0; kk < 16; kk++) {
            float4 a = *(const float4*)&As[kk][ty*4];
            float4 b = *(const float4*)&Bs[kk][tx*4];
            float av[4] = {a.x,a.y,a.z,a.w};
            float bv[4] = {b.x,b.y,b.z,b.w};
            #pragma unroll
            for (int i=0;i<4;i++)
                #pragma unroll
                for (int j=0;j<4;j++) acc[i][j] = fmaf(av[i], bv[j], acc[i][j]);
        }
    }
    #pragma unroll
    for (int i=0;i<4;i++) {
        int row = m0 + ty*4 + i;
        float* outp = &g_hW[(size_t)row*H2 + n0 + tx*4];
        #pragma unroll
        for (int j=0;j<4;j++) outp[j] = acc[i][j];
    }
}

// ---------------- final sequential scan (independent per b) -----------------
__global__ void k_scan(float* __restrict__ out) {
    __shared__ float summ[H2];
    __shared__ float red[8];
    __shared__ float probsh;
    int b = blockIdx.x;
    int tid = threadIdx.x;
    int lane = tid & 31, wrp = tid >> 5;
    #pragma unroll
    for (int q = 0; q < 4; q++) summ[tid + q*256] = 0.f;
    __syncthreads();
    for (int t = 0; t < TT; t++) {
        const float* hw = &g_hW[((size_t)t*BB + b)*H2];
        float part = 0.f;
        #pragma unroll
        for (int q = 0; q < 4; q++) {
            int k = tid + q*256;
            part += hw[k]*tanhf(summ[k]);
        }
        #pragma unroll
        for (int o = 16; o > 0; o >>= 1) part += __shfl_down_sync(0xffffffffu, part, o);
        if (lane == 0) red[wrp] = part;
        __syncthreads();
        if (tid == 0) {
            float nov = 0.f;
            #pragma unroll
            for (int r = 0; r < 8; r++) nov += red[r];
            float prob = 1.f/(1.f+expf(-(g_s0[b*TT + t] - nov)));
            out[b*TT + t] = prob;
            probsh = prob;
        }
        __syncthreads();
        float p = probsh;
        const float* sp = &g_sents[((size_t)t*BB + b)*H2];
        #pragma unroll
        for (int q = 0; q < 4; q++) {
            int k = tid + q*256;
            summ[k] += p * sp[k];
        }
        __syncthreads();
    }
}

// ---------------- launcher ---------------------------------------------------
extern "C" void kernel_launch(void* const* d_in, const int* in_sizes, int n_in,
                              void* d_out, int out_size) {
    const float* emb      = (const float*)d_in[0];
    const float* w_ih_f   = (const float*)d_in[2];
    const float* w_hh_f   = (const float*)d_in[3];
    const float* b_f      = (const float*)d_in[4];
    const float* w_ih_b   = (const float*)d_in[5];
    const float* w_hh_b   = (const float*)d_in[6];
    const float* b_b      = (const float*)d_in[7];
    const float* W_fdoc   = (const float*)d_in[8];
    const float* b_fdoc   = (const float*)d_in[9];
    const float* pos_emb  = (const float*)d_in[10];
    const float* w_content= (const float*)d_in[11];
    const float* W_sal    = (const float*)d_in[12];
    const float* W_nov    = (const float*)d_in[13];
    const float* w_abs    = (const float*)d_in[14];
    const float* bias     = (const float*)d_in[15];
    float* out = (float*)d_out;

    k_zero<<<1024, 256>>>();

    dim3 gpre(GG/64, TB/64);               // 32 x 256
    k_gemm_pre<<<gpre, 256>>>(emb, w_ih_f, b_f, 0);
    k_gemm_pre<<<gpre, 256>>>(emb, w_ih_b, b_b, 1);

    for (int s = 0; s < BB; s++) {
        dim3 grec(GG/64, TT/64, 2);        // 32 x 4 x 2
        k_gemm_rec<<<grec, 256>>>(w_hh_f, w_hh_b, s & 1, s, 63 - s);
        k_act<<<1024, 256>>>((s + 1) & 1, s, 63 - s);
    }

    k_docmean<<<256, 256>>>();
    k_doc<<<8192, 256>>>(W_fdoc, b_fdoc);
    k_u<<<8192, 256>>>(W_sal, w_content);
    k_absp<<<1, 256>>>(pos_emb, w_abs);
    k_s0<<<2048, 256>>>(bias);

    dim3 gnn(H2/64, TB/64);                // 16 x 256
    k_gemm_nn<<<gnn, 256>>>(W_nov);

    k_scan<<<BB, 256>>>(out);
}